// round 17
// baseline (speedup 1.0000x reference)
#include <cuda_runtime.h>
#include <cstdint>

#define B_     32
#define CIN_   256
#define COUT_  256
#define HW_    56
#define WN_    (COUT_ * CIN_ * 9)
#define BN_EPS 1e-5f

typedef unsigned long long ull;

// Scratch (allocation-free __device__ globals)
__device__ int   g_maxbits;                    // static zero; atomicMax idempotent
__device__ float g_U[16 * CIN_ * COUT_];       // [p][ci][co] Winograd weights
__device__ float g_scale[COUT_];
__device__ float g_bias[COUT_];

// ---------------------------------------------------------------------------
__global__ void wmax_kernel(const float* __restrict__ w) {
    float m = 0.0f;
    for (int i = blockIdx.x * blockDim.x + threadIdx.x; i < WN_;
         i += gridDim.x * blockDim.x)
        m = fmaxf(m, fabsf(w[i]));
    #pragma unroll
    for (int o = 16; o > 0; o >>= 1)
        m = fmaxf(m, __shfl_xor_sync(0xFFFFFFFFu, m, o));
    if ((threadIdx.x & 31) == 0)
        atomicMax(&g_maxbits, __float_as_int(m));   // nonneg: int order ok
}

// DoReFa quant + Winograd weight transform U = G g G^T  (per co,ci)
__global__ void uprep_kernel(const float* __restrict__ w) {
    int idx = blockIdx.x * blockDim.x + threadIdx.x;   // 65536
    int co = idx >> 8, ci = idx & 255;
    float T = tanhf(__int_as_float(g_maxbits));
    float q[3][3];
    #pragma unroll
    for (int ky = 0; ky < 3; ++ky)
        #pragma unroll
        for (int kx = 0; kx < 3; ++kx) {
            float t = tanhf(w[(co * 256 + ci) * 9 + ky * 3 + kx]);
            float u = t / (2.0f * T) + 0.5f;
            q[ky][kx] = 2.0f * (rintf(u * 15.0f) / 15.0f) - 1.0f;
        }
    float a[4][3];
    #pragma unroll
    for (int c = 0; c < 3; ++c) {
        a[0][c] = q[0][c];
        a[1][c] = 0.5f * (q[0][c] + q[1][c] + q[2][c]);
        a[2][c] = 0.5f * (q[0][c] - q[1][c] + q[2][c]);
        a[3][c] = q[2][c];
    }
    #pragma unroll
    for (int i = 0; i < 4; ++i) {
        float u0 = a[i][0];
        float u1 = 0.5f * (a[i][0] + a[i][1] + a[i][2]);
        float u2 = 0.5f * (a[i][0] - a[i][1] + a[i][2]);
        float u3 = a[i][2];
        g_U[((i * 4 + 0) * 256 + ci) * 256 + co] = u0;
        g_U[((i * 4 + 1) * 256 + ci) * 256 + co] = u1;
        g_U[((i * 4 + 2) * 256 + ci) * 256 + co] = u2;
        g_U[((i * 4 + 3) * 256 + ci) * 256 + co] = u3;
    }
}

__global__ void bnprep_kernel(const float* __restrict__ gamma,
                              const float* __restrict__ beta,
                              const float* __restrict__ mean,
                              const float* __restrict__ var) {
    int c = threadIdx.x;
    float inv = gamma[c] * rsqrtf(var[c] + BN_EPS);
    g_scale[c] = inv;
    g_bias[c]  = beta[c] - mean[c] * inv;
}

// ---------------------------------------------------------------------------
#define FFMA2(d, a, b) \
    asm("fma.rn.f32x2 %0, %1, %2, %0;" : "+l"(d) : "l"(a), "l"(b))

static __device__ __forceinline__ void cp16(uint32_t dst, const void* src) {
    asm volatile("cp.async.cg.shared.global [%0], [%1], 16;"
                 :: "r"(dst), "l"(src));
}
#define CP_COMMIT() asm volatile("cp.async.commit_group;")
#define CP_WAIT(n)  asm volatile("cp.async.wait_group %0;" :: "n"(n) : "memory")

// SMEM layout (bytes):
//  W x2: [ci8 x10240][p16 x640][lc8 x80 (64B data,16B pad)]    = 163840
//  V x2: [ci8 x2320][p16 x144][tile16 x8]  f32x2 splats        = 37120
//  X x2: [ci8 x480][10r][12c pad] f32                          = 7680
//  BN: 1024
//  Epilogue overlay (after loop): M [p16 x8208][tile16 x512][cp64 x8]
#define WD_SZ   81920
#define VS_OFF  163840
#define VS_BUF  18560
#define VS_CI   2320
#define XS_OFF  200960
#define XS_BUF  3840
#define BN_OFF  208640
#define SMEM_TOT 209664
#define MP_STR  8208

extern __shared__ char smem[];

// ---------------------------------------------------------------------------
// Fused Winograd F(2x2,3x3) conv + BN + PACT.  CTA: 512 thr, 1/SM.
// Tile: image n, 8x8 px (16 tiles), 128-co half. Single barrier per chunk:
// GEMM(ch) || transform(ch+1) || X-LDG(ch+2) || cp.async W(ch+1).
// GEMM: warp = p; lane = lt4 x lc8; thread = 4 tiles x 8 co-pairs = 32 accs.
// Transform: 512 quarter-tasks (tile16 x ci8 x row4), trow warp-uniform.
// ---------------------------------------------------------------------------
__global__ void __launch_bounds__(512, 1)
conv_wino_kernel(const float* __restrict__ x,
                 const float* __restrict__ alpha,
                 float* __restrict__ out) {
    const int tid  = threadIdx.x;
    const int p    = tid >> 5;
    const int lane = tid & 31;
    const int lt   = lane >> 3;
    const int lc   = lane & 7;
    const int ox   = (blockIdx.x % 7) * 8, oy = (blockIdx.x / 7) * 8;
    const int coH  = blockIdx.y;
    const int n    = blockIdx.z;

    const uint32_t sb = (uint32_t)__cvta_generic_to_shared(smem);
    float* sScale = (float*)(smem + BN_OFF);
    float* sBias  = (float*)(smem + BN_OFF + 512);
    if (tid < 128) {
        sScale[tid] = g_scale[coH * 128 + tid];
        sBias[tid]  = g_bias[coH * 128 + tid];
    }

    const float* xn = x + (size_t)n * CIN_ * 3136;
    const float* Ub = g_U + (size_t)coH * 128;

    ull acc[4][8];
    #pragma unroll
    for (int t = 0; t < 4; ++t)
        #pragma unroll
        for (int c = 0; c < 8; ++c) acc[t][c] = 0ull;

    // transform quarter-task: 512 = tile16 x ci8 x row4
    const int ttile = tid & 15;
    const int tci   = (tid >> 4) & 7;
    const int trow  = tid >> 7;          // warp-uniform
    const int tty   = ttile >> 2, ttx = ttile & 3;
    int r_a, r_b; float s_a, s_b;
    if      (trow == 0) { r_a = 0; r_b = 2; s_a = 1.0f;  s_b = -1.0f; }
    else if (trow == 1) { r_a = 1; r_b = 2; s_a = 1.0f;  s_b =  1.0f; }
    else if (trow == 2) { r_a = 1; r_b = 2; s_a = -1.0f; s_b =  1.0f; }
    else                { r_a = 1; r_b = 3; s_a = 1.0f;  s_b = -1.0f; }
    const int txoff = (2 * tty) * 12 + 2 * ttx;

    // ---- prologue ----
    // stage Xs[0] = X(0)
    #pragma unroll
    for (int k = 0; k < 2; ++k) {
        int i = tid + k * 512;
        if (i < 800) {
            int ci = i / 100, rem = i % 100, r = rem / 10, c = rem % 10;
            int gy = oy - 1 + r, gx = ox - 1 + c;
            float v = 0.0f;
            if (gy >= 0 && gy < HW_ && gx >= 0 && gx < HW_)
                v = xn[(size_t)ci * 3136 + gy * 56 + gx];
            ((float*)(smem + XS_OFF))[ci * 120 + r * 12 + c] = v;
        }
    }
    // cp W(0) -> buf0 : 4096 granules, 8/thread
    #pragma unroll
    for (int k = 0; k < 8; ++k) {
        int i = tid + k * 512;
        int ci = i >> 9, rem = i & 511, pp = rem >> 5, g = rem & 31;
        cp16(sb + ci * 10240 + pp * 640 + (g >> 2) * 80 + (g & 3) * 16,
             Ub + ((size_t)(pp * 256 + ci) * 256) + g * 4);
    }
    CP_COMMIT();
    __syncthreads();
    // transform V(0) from Xs[0]
    {
        const float* Xb = (float*)(smem + XS_OFF) + tci * 120 + txoff;
        float2 A0 = *(float2*)(Xb + r_a * 12);
        float2 A1 = *(float2*)(Xb + r_a * 12 + 2);
        float2 B0 = *(float2*)(Xb + r_b * 12);
        float2 B1 = *(float2*)(Xb + r_b * 12 + 2);
        float t0 = s_a * A0.x + s_b * B0.x, t1 = s_a * A0.y + s_b * B0.y;
        float t2 = s_a * A1.x + s_b * B1.x, t3 = s_a * A1.y + s_b * B1.y;
        char* vb = smem + VS_OFF + tci * VS_CI + ttile * 8;
        float2 v;
        v.x = v.y = t0 - t2; *(float2*)(vb + (trow * 4 + 0) * 144) = v;
        v.x = v.y = t1 + t2; *(float2*)(vb + (trow * 4 + 1) * 144) = v;
        v.x = v.y = t2 - t1; *(float2*)(vb + (trow * 4 + 2) * 144) = v;
        v.x = v.y = t1 - t3; *(float2*)(vb + (trow * 4 + 3) * 144) = v;
    }
    // stage Xs[1] = X(1)
    #pragma unroll
    for (int k = 0; k < 2; ++k) {
        int i = tid + k * 512;
        if (i < 800) {
            int ci = i / 100, rem = i % 100, r = rem / 10, c = rem % 10;
            int gy = oy - 1 + r, gx = ox - 1 + c;
            float v = 0.0f;
            if (gy >= 0 && gy < HW_ && gx >= 0 && gx < HW_)
                v = xn[(size_t)(8 + ci) * 3136 + gy * 56 + gx];
            ((float*)(smem + XS_OFF + XS_BUF))[ci * 120 + r * 12 + c] = v;
        }
    }
    __syncthreads();

    // ---- main loop: one barrier per chunk ----
    for (int ch = 0; ch < 32; ++ch) {
        const int buf = ch & 1;
        if (ch < 31) {
            uint32_t dst = sb + (buf ^ 1) * WD_SZ;
            const float* Un = Ub + (size_t)(ch + 1) * 8 * 256;
            #pragma unroll
            for (int k = 0; k < 8; ++k) {
                int i = tid + k * 512;
                int ci = i >> 9, rem = i & 511, pp = rem >> 5, g = rem & 31;
                cp16(dst + ci * 10240 + pp * 640 + (g >> 2) * 80 + (g & 3) * 16,
                     Un + ((size_t)pp * 256 + ci) * 256 + g * 4);
            }
            CP_COMMIT();
            CP_WAIT(1);
        } else {
            CP_WAIT(0);
        }

        // X(ch+2) LDGs issued early (latency hidden by GEMM)
        float xv0 = 0.0f, xv1 = 0.0f;
        int xi0 = 0, xi1 = 0;
        if (ch < 30) {
            const float* xc = xn + (size_t)(ch + 2) * 8 * 3136;
            {
                int i = tid;
                int ci = i / 100, rem = i % 100, r = rem / 10, c = rem % 10;
                int gy = oy - 1 + r, gx = ox - 1 + c;
                xi0 = ci * 120 + r * 12 + c;
                if (gy >= 0 && gy < HW_ && gx >= 0 && gx < HW_)
                    xv0 = xc[(size_t)ci * 3136 + gy * 56 + gx];
            }
            if (tid < 288) {
                int i = tid + 512;
                int ci = i / 100, rem = i % 100, r = rem / 10, c = rem % 10;
                int gy = oy - 1 + r, gx = ox - 1 + c;
                xi1 = ci * 120 + r * 12 + c;
                if (gy >= 0 && gy < HW_ && gx >= 0 && gx < HW_)
                    xv1 = xc[(size_t)ci * 3136 + gy * 56 + gx];
            }
        }

        // ---- GEMM(ch) ----
        {
            const char* vb = smem + VS_OFF + buf * VS_BUF + p * 144 + lt * 32;
            const char* wb = smem + buf * WD_SZ + p * 640 + lc * 80;
            #pragma unroll
            for (int ci = 0; ci < 8; ++ci) {
                ulonglong2 a0 = *(const ulonglong2*)(vb + ci * VS_CI);
                ulonglong2 a1 = *(const ulonglong2*)(vb + ci * VS_CI + 16);
                ull v[4] = { a0.x, a0.y, a1.x, a1.y };
                const char* wc = wb + ci * 10240;
                ulonglong2 w0 = *(const ulonglong2*)(wc);
                ulonglong2 w1 = *(const ulonglong2*)(wc + 16);
                ulonglong2 w2 = *(const ulonglong2*)(wc + 32);
                ulonglong2 w3 = *(const ulonglong2*)(wc + 48);
                ull w[8] = { w0.x, w0.y, w1.x, w1.y, w2.x, w2.y, w3.x, w3.y };
                #pragma unroll
                for (int t = 0; t < 4; ++t)
                    #pragma unroll
                    for (int c = 0; c < 8; ++c)
                        FFMA2(acc[t][c], v[t], w[c]);
            }
        }

        // ---- transform V(ch+1) from Xs[(ch+1)&1] ----
        if (ch < 31) {
            const float* Xb = (float*)(smem + XS_OFF + ((ch + 1) & 1) * XS_BUF)
                              + tci * 120 + txoff;
            float2 A0 = *(float2*)(Xb + r_a * 12);
            float2 A1 = *(float2*)(Xb + r_a * 12 + 2);
            float2 B0 = *(float2*)(Xb + r_b * 12);
            float2 B1 = *(float2*)(Xb + r_b * 12 + 2);
            float t0 = s_a * A0.x + s_b * B0.x, t1 = s_a * A0.y + s_b * B0.y;
            float t2 = s_a * A1.x + s_b * B1.x, t3 = s_a * A1.y + s_b * B1.y;
            char* vb = smem + VS_OFF + ((ch + 1) & 1) * VS_BUF +
                       tci * VS_CI + ttile * 8;
            float2 v;
            v.x = v.y = t0 - t2; *(float2*)(vb + (trow * 4 + 0) * 144) = v;
            v.x = v.y = t1 + t2; *(float2*)(vb + (trow * 4 + 1) * 144) = v;
            v.x = v.y = t2 - t1; *(float2*)(vb + (trow * 4 + 2) * 144) = v;
            v.x = v.y = t1 - t3; *(float2*)(vb + (trow * 4 + 3) * 144) = v;
        }

        // ---- stash X(ch+2) -> Xs[ch&1] ----
        if (ch < 30) {
            float* Xd = (float*)(smem + XS_OFF + buf * XS_BUF);
            Xd[xi0] = xv0;
            if (tid < 288) Xd[xi1] = xv1;
        }
        __syncthreads();
    }

    // ---- epilogue: M scatter -> inverse transform + BN + PACT -> gmem ----
    {
        char* mb = smem + p * MP_STR;
        #pragma unroll
        for (int t = 0; t < 4; ++t)
            #pragma unroll
            for (int j = 0; j < 8; ++j)
                *(ull*)(mb + (lt * 4 + t) * 512 + (lc * 8 + j) * 8) = acc[t][j];
    }
    __syncthreads();

    const float aV   = __ldg(alpha);
    const float r15a = 15.0f / aV;
    const float a15  = aV / 15.0f;

    #pragma unroll
    for (int kk = 0; kk < 2; ++kk) {
        int task = tid + kk * 512;       // 1024 = tile16 x cp64
        int cp = task & 63, tile = task >> 6;
        int tty2 = tile >> 2, ttx2 = tile & 3;
        float m0[16], m1[16];
        #pragma unroll
        for (int pp = 0; pp < 16; ++pp) {
            ull mv = *(ull*)(smem + pp * MP_STR + tile * 512 + cp * 8);
            asm("mov.b64 {%0, %1}, %2;" : "=f"(m0[pp]), "=f"(m1[pp]) : "l"(mv));
        }
        #pragma unroll
        for (int comp = 0; comp < 2; ++comp) {
            const float* m = comp ? m1 : m0;
            const int col = cp * 2 + comp;
            const float sc = sScale[col], bi = sBias[col];
            float r0[4], r1[4];
            #pragma unroll
            for (int j = 0; j < 4; ++j) {
                r0[j] = m[0 * 4 + j] + m[1 * 4 + j] + m[2 * 4 + j];
                r1[j] = m[1 * 4 + j] - m[2 * 4 + j] - m[3 * 4 + j];
            }
            float y00 = r0[0] + r0[1] + r0[2];
            float y01 = r0[1] - r0[2] - r0[3];
            float y10 = r1[0] + r1[1] + r1[2];
            float y11 = r1[1] - r1[2] - r1[3];
            y00 = rintf(fminf(fmaxf(y00 * sc + bi, 0.0f), aV) * r15a) * a15;
            y01 = rintf(fminf(fmaxf(y01 * sc + bi, 0.0f), aV) * r15a) * a15;
            y10 = rintf(fminf(fmaxf(y10 * sc + bi, 0.0f), aV) * r15a) * a15;
            y11 = rintf(fminf(fmaxf(y11 * sc + bi, 0.0f), aV) * r15a) * a15;
            float* op = out + (size_t)(n * COUT_ + coH * 128 + col) * 3136 +
                        (oy + 2 * tty2) * 56 + ox + 2 * ttx2;
            *(float2*)(op)      = make_float2(y00, y01);
            *(float2*)(op + 56) = make_float2(y10, y11);
        }
    }
}

// ---------------------------------------------------------------------------
extern "C" void kernel_launch(void* const* d_in, const int* in_sizes, int n_in,
                              void* d_out, int out_size) {
    const float* x      = (const float*)d_in[0];
    const float* weight = (const float*)d_in[1];
    const float* gamma  = (const float*)d_in[2];
    const float* beta   = (const float*)d_in[3];
    const float* rmean  = (const float*)d_in[4];
    const float* rvar   = (const float*)d_in[5];
    const float* alpha  = (const float*)d_in[6];
    float* out = (float*)d_out;

    wmax_kernel<<<576, 256>>>(weight);
    uprep_kernel<<<256, 256>>>(weight);
    bnprep_kernel<<<1, 256>>>(gamma, beta, rmean, rvar);

    cudaFuncSetAttribute(conv_wino_kernel,
                         cudaFuncAttributeMaxDynamicSharedMemorySize, SMEM_TOT);
    dim3 grid(49, 2, B_);
    conv_wino_kernel<<<grid, 512, SMEM_TOT>>>(x, alpha, out);
}